// round 13
// baseline (speedup 1.0000x reference)
#include <cuda_runtime.h>
#include <cuda_bf16.h>
#include <math.h>

// ---------------------------------------------------------------------------
#define NB      512
#define NA      256
#define CMAX    0.05f
#define NITERS  300
#define NPOW    30
#define NEWT    12

__device__ float dRf[(size_t)NB * 128 * 256];   // rows 0..127 of Q, full width
__device__ float dDf[(size_t)NB * 128 * 128];   // Q[128+i][128+j]

// integer warp reductions (sm_80+)
__device__ __forceinline__ int rsum_s32(int x) {
    int r;
    asm("redux.sync.add.s32 %0, %1, 0xffffffff;" : "=r"(r) : "r"(x));
    return r;
}
__device__ __forceinline__ int rmin_s32(int x) {
    int r;
    asm("redux.sync.min.s32 %0, %1, 0xffffffff;" : "=r"(r) : "r"(x));
    return r;
}
__device__ __forceinline__ int rmax_s32(int x) {
    int r;
    asm("redux.sync.max.s32 %0, %1, 0xffffffff;" : "=r"(r) : "r"(x));
    return r;
}
__device__ __forceinline__ int f2ord(float x) {
    int i = __float_as_int(x);
    return i ^ ((i >> 31) & 0x7fffffff);
}
__device__ __forceinline__ float ord2f(int i) {
    return __int_as_float(i ^ ((i >> 31) & 0x7fffffff));
}

// ---------------------------------------------------------------------------
// Kernel 1: Q = A^T A  (tiles (0,0),(0,1),(1,1); Q symmetric)
// ---------------------------------------------------------------------------
__global__ __launch_bounds__(256) void qgemm_kernel(const float* __restrict__ A) {
    const int tile = blockIdx.x;
    const int b    = blockIdx.y;
    const int cj   = (tile == 2) ? 128 : 0;
    const int ck   = (tile == 0) ? 0   : 128;

    __shared__ float sA[16][128];
    __shared__ float sB[16][128];

    const int tid = threadIdx.x;
    const int tx  = tid & 15;
    const int ty  = tid >> 4;

    float acc[8][8];
#pragma unroll
    for (int i = 0; i < 8; ++i)
#pragma unroll
        for (int j = 0; j < 8; ++j) acc[i][j] = 0.f;

    const float* __restrict__ Ab = A + (size_t)b * NA * NA;

    for (int ic = 0; ic < NA; ic += 16) {
#pragma unroll
        for (int u = 0; u < 2; ++u) {
            int idx = tid * 8 + u * 4;
            int r   = idx >> 7;
            int cc  = idx & 127;
            *(float4*)&sA[r][cc] = *(const float4*)&Ab[(size_t)(ic + r) * NA + cj + cc];
            *(float4*)&sB[r][cc] = *(const float4*)&Ab[(size_t)(ic + r) * NA + ck + cc];
        }
        __syncthreads();

#pragma unroll
        for (int kk = 0; kk < 16; ++kk) {
            float a8[8], b8[8];
            const float4* pa = (const float4*)&sA[kk][ty * 8];
            const float4* pb = (const float4*)&sB[kk][tx * 8];
            float4 a0 = pa[0], a1 = pa[1];
            float4 b0 = pb[0], b1 = pb[1];
            a8[0]=a0.x; a8[1]=a0.y; a8[2]=a0.z; a8[3]=a0.w;
            a8[4]=a1.x; a8[5]=a1.y; a8[6]=a1.z; a8[7]=a1.w;
            b8[0]=b0.x; b8[1]=b0.y; b8[2]=b0.z; b8[3]=b0.w;
            b8[4]=b1.x; b8[5]=b1.y; b8[6]=b1.z; b8[7]=b1.w;
#pragma unroll
            for (int i = 0; i < 8; ++i)
#pragma unroll
                for (int j = 0; j < 8; ++j)
                    acc[i][j] = fmaf(a8[i], b8[j], acc[i][j]);
        }
        __syncthreads();
    }

#pragma unroll
    for (int i = 0; i < 8; ++i) {
        int row = ty * 8 + i;
        float4 v0 = make_float4(acc[i][0], acc[i][1], acc[i][2], acc[i][3]);
        float4 v1 = make_float4(acc[i][4], acc[i][5], acc[i][6], acc[i][7]);
        if (tile < 2) {
            float* dst = dRf + ((size_t)b * 128 + row) * 256 + ck + tx * 8;
            *(float4*)dst       = v0;
            *(float4*)(dst + 4) = v1;
        } else {
            float* dst = dDf + ((size_t)b * 128 + row) * 128 + tx * 8;
            *(float4*)dst       = v0;
            *(float4*)(dst + 4) = v1;
        }
    }
}

// ---------------------------------------------------------------------------
// Kernel 2: per-batch FISTA. 1024 threads. Balanced matvec with partial
// register-cached Q on warps 8..31; Newton core identical to the R10 passer.
// ---------------------------------------------------------------------------
#define TPB 1024
#define RP 260
#define DP 132
#define SR_ELEMS (128 * RP)
#define SD_ELEMS (128 * DP)
#define SP_ELEMS 1792
#define SMEM_FLOATS (SR_ELEMS + SD_ELEMS + 256 + SP_ELEMS + 32)
#define SMEM_BYTES (SMEM_FLOATS * 4)

__device__ __forceinline__ float blk_sum1024(float a, float* red, int t) {
#pragma unroll
    for (int o = 16; o > 0; o >>= 1)
        a += __shfl_xor_sync(0xffffffffu, a, o);
    if ((t & 31) == 0) red[t >> 5] = a;
    __syncthreads();
    float r = 0.f;
#pragma unroll
    for (int i = 0; i < 32; ++i) r += red[i];
    __syncthreads();
    return r;
}

// matvec producer: warps 0..15 rows of R (k-quarters), 16..23 rows of D,
// 24..31 R_ur^T row-accumulation. Warps >=8 use a 4-float4 register cache.
__device__ __forceinline__ void matvec_produce(const float* __restrict__ sR,
                                               const float* __restrict__ sD,
                                               const float* __restrict__ sy,
                                               float* __restrict__ sp,
                                               int wid, int lane,
                                               const float4* __restrict__ qc) {
    const float4* __restrict__ y4 = (const float4*)sy;
    if (wid < 16) {
        const int q = wid >> 2;
        const int u = ((wid & 3) << 5) + lane;
        const float4* __restrict__ qr = (const float4*)(sR + u * RP) + q * 16;
        const float4* __restrict__ yy = y4 + q * 16;
        float g0 = 0.f, g1 = 0.f, g2 = 0.f, g3 = 0.f;
        if (wid >= 8) {
#pragma unroll
            for (int k = 0; k < 4; ++k) {
                float4 qv = qc[k], yv = yy[k];
                g0 = fmaf(qv.x, yv.x, g0); g1 = fmaf(qv.y, yv.y, g1);
                g2 = fmaf(qv.z, yv.z, g2); g3 = fmaf(qv.w, yv.w, g3);
            }
#pragma unroll
            for (int k = 4; k < 16; ++k) {
                float4 qv = qr[k], yv = yy[k];
                g0 = fmaf(qv.x, yv.x, g0); g1 = fmaf(qv.y, yv.y, g1);
                g2 = fmaf(qv.z, yv.z, g2); g3 = fmaf(qv.w, yv.w, g3);
            }
        } else {
#pragma unroll
            for (int k = 0; k < 16; ++k) {
                float4 qv = qr[k], yv = yy[k];
                g0 = fmaf(qv.x, yv.x, g0); g1 = fmaf(qv.y, yv.y, g1);
                g2 = fmaf(qv.z, yv.z, g2); g3 = fmaf(qv.w, yv.w, g3);
            }
        }
        sp[q * 128 + u] = (g0 + g1) + (g2 + g3);
    } else if (wid < 24) {
        const int w2 = wid - 16;
        const int hh = w2 >> 2;
        const int ul = ((w2 & 3) << 5) + lane;
        const float4* __restrict__ dr = (const float4*)(sD + ul * DP) + hh * 16;
        const float4* __restrict__ yy = y4 + 32 + hh * 16;
        float g0 = 0.f, g1 = 0.f, g2 = 0.f, g3 = 0.f;
#pragma unroll
        for (int k = 0; k < 4; ++k) {
            float4 qv = qc[k], yv = yy[k];
            g0 = fmaf(qv.x, yv.x, g0); g1 = fmaf(qv.y, yv.y, g1);
            g2 = fmaf(qv.z, yv.z, g2); g3 = fmaf(qv.w, yv.w, g3);
        }
#pragma unroll
        for (int k = 4; k < 16; ++k) {
            float4 qv = dr[k], yv = yy[k];
            g0 = fmaf(qv.x, yv.x, g0); g1 = fmaf(qv.y, yv.y, g1);
            g2 = fmaf(qv.z, yv.z, g2); g3 = fmaf(qv.w, yv.w, g3);
        }
        sp[512 + hh * 128 + ul] = (g0 + g1) + (g2 + g3);
    } else {
        const int w = wid - 24;
        const float4* __restrict__ sR4 = (const float4*)sR;
        float4 acc = make_float4(0.f, 0.f, 0.f, 0.f);
        const int k0 = w * 16;
        // kb = 0 from register cache
        {
            float4 yv = y4[k0 >> 2];
            acc.x = fmaf(qc[0].x, yv.x, acc.x); acc.y = fmaf(qc[0].y, yv.x, acc.y);
            acc.z = fmaf(qc[0].z, yv.x, acc.z); acc.w = fmaf(qc[0].w, yv.x, acc.w);
            acc.x = fmaf(qc[1].x, yv.y, acc.x); acc.y = fmaf(qc[1].y, yv.y, acc.y);
            acc.z = fmaf(qc[1].z, yv.y, acc.z); acc.w = fmaf(qc[1].w, yv.y, acc.w);
            acc.x = fmaf(qc[2].x, yv.z, acc.x); acc.y = fmaf(qc[2].y, yv.z, acc.y);
            acc.z = fmaf(qc[2].z, yv.z, acc.z); acc.w = fmaf(qc[2].w, yv.z, acc.w);
            acc.x = fmaf(qc[3].x, yv.w, acc.x); acc.y = fmaf(qc[3].y, yv.w, acc.y);
            acc.z = fmaf(qc[3].z, yv.w, acc.z); acc.w = fmaf(qc[3].w, yv.w, acc.w);
        }
#pragma unroll
        for (int kb = 1; kb < 4; ++kb) {
            float4 yv = y4[(k0 >> 2) + kb];
#pragma unroll
            for (int kk = 0; kk < 4; ++kk) {
                const int k = k0 + kb * 4 + kk;
                float4 qv = sR4[k * 65 + 32 + lane];
                float yk = (kk == 0) ? yv.x : (kk == 1) ? yv.y
                          : (kk == 2) ? yv.z : yv.w;
                acc.x = fmaf(qv.x, yk, acc.x);
                acc.y = fmaf(qv.y, yk, acc.y);
                acc.z = fmaf(qv.z, yk, acc.z);
                acc.w = fmaf(qv.w, yk, acc.w);
            }
        }
        ((float4*)(sp + 768 + w * 128))[lane] = acc;
    }
}

// gather g_c from partials (lane-consecutive reads, conflict-free)
__device__ __forceinline__ float gather_g(const float* __restrict__ sp, int c) {
    if (c < 128) {
        return (sp[c] + sp[128 + c]) + (sp[256 + c] + sp[384 + c]);
    } else {
        const int cl = c - 128;
        float a = sp[512 + cl] + sp[640 + cl];
        float b0 = sp[768 + cl]  + sp[896 + cl];
        float b1 = sp[1024 + cl] + sp[1152 + cl];
        float b2 = sp[1280 + cl] + sp[1408 + cl];
        float b3 = sp[1536 + cl] + sp[1664 + cl];
        return a + ((b0 + b1) + (b2 + b3));
    }
}

__global__ __launch_bounds__(TPB, 1) void fista_kernel(float* __restrict__ out) {
    extern __shared__ float sm[];
    float* sR  = sm;
    float* sD  = sm + SR_ELEMS;
    float* sy  = sD + SD_ELEMS;          // 256
    float* sp  = sy + 256;               // 1792 partials
    float* red = sp + SP_ELEMS;          // 32

    const int b    = blockIdx.x;
    const int t    = threadIdx.x;
    const int lane = t & 31;
    const int wid  = t >> 5;             // 0..31

    // --- load compressed Q into padded SMEM ---
    {
        const float4* __restrict__ gR = (const float4*)(dRf + (size_t)b * 128 * 256);
        float4* sR4 = (float4*)sR;
        for (int i = t; i < 128 * 64; i += TPB) {
            int r = i >> 6, c = i & 63;
            sR4[r * 65 + c] = gR[i];
        }
        const float4* __restrict__ gD = (const float4*)(dDf + (size_t)b * 128 * 128);
        float4* sD4 = (float4*)sD;
        for (int i = t; i < 128 * 32; i += TPB) {
            int r = i >> 5, c = i & 31;
            sD4[r * 33 + c] = gD[i];
        }
    }
    if (t < 256) sy[t] = 0.0625f;   // 1/sqrt(256)
    __syncthreads();

    // --- per-role register cache of the first 4 float4 of each warp's Q slice
    float4 qcache[4];
    if (wid >= 8 && wid < 16) {
        const int q = wid >> 2;
        const int u = ((wid & 3) << 5) + lane;
        const float4* qr = (const float4*)(sR + u * RP) + q * 16;
#pragma unroll
        for (int k = 0; k < 4; ++k) qcache[k] = qr[k];
    } else if (wid >= 16 && wid < 24) {
        const int w2 = wid - 16;
        const int hh = w2 >> 2;
        const int ul = ((w2 & 3) << 5) + lane;
        const float4* dr = (const float4*)(sD + ul * DP) + hh * 16;
#pragma unroll
        for (int k = 0; k < 4; ++k) qcache[k] = dr[k];
    } else if (wid >= 24) {
        const int w = wid - 24;
        const int k0 = w * 16;
        const float4* sR4 = (const float4*)sR;
#pragma unroll
        for (int k = 0; k < 4; ++k) qcache[k] = sR4[(k0 + k) * 65 + 32 + lane];
    }

    // --- power iteration for lambda_max ---
    for (int pi = 0; pi < NPOW; ++pi) {
        matvec_produce(sR, sD, sy, sp, wid, lane, qcache);
        __syncthreads();
        float g = (t < 256) ? gather_g(sp, t) : 0.f;
        float nr = blk_sum1024((t < 256) ? g * g : 0.f, red, t);
        if (t < 256) sy[t] = g * (1.f / (sqrtf(nr) + 1e-12f));
        __syncthreads();
    }
    float s2;
    {
        matvec_produce(sR, sD, sy, sp, wid, lane, qcache);
        __syncthreads();
        float g = (t < 256) ? gather_g(sp, t) : 0.f;
        float lmax = blk_sum1024((t < 256) ? sy[t] * g : 0.f, red, t);
        s2 = 2.f / (2.f * lmax + 1e-12f);
    }

    // --- FISTA ---
    const float FS  = 67108864.f;          // 2^26 fixed-point scale (R10 passer)
    const float FSI = 1.f / 67108864.f;
    float w_loc[8], y_loc[8];
#pragma unroll
    for (int j = 0; j < 8; ++j) { w_loc[j] = 1.f / 256.f; y_loc[j] = 1.f / 256.f; }
    float tk = 1.f;
    if (t < 256) sy[t] = 1.f / 256.f;
    __syncthreads();

#pragma unroll 1
    for (int it = 0; it < NITERS; ++it) {
        matvec_produce(sR, sD, sy, sp, wid, lane, qcache);
        __syncthreads();

        if (wid < 8) {   // projection warps: each holds all 256 coords
            float v[8];
#pragma unroll
            for (int j = 0; j < 8; ++j) {
                int c = lane + 32 * j;
                v[j] = y_loc[j] - s2 * gather_g(sp, c);
            }

            // bracket via REDUX min/max on order-mapped ints
            float mn0 = fminf(fminf(v[0], v[1]), fminf(v[2], v[3]));
            float mn1 = fminf(fminf(v[4], v[5]), fminf(v[6], v[7]));
            float mx0 = fmaxf(fmaxf(v[0], v[1]), fmaxf(v[2], v[3]));
            float mx1 = fmaxf(fmaxf(v[4], v[5]), fmaxf(v[6], v[7]));
            float mn = ord2f(rmin_s32(f2ord(fminf(mn0, mn1))));
            float mx = ord2f(rmax_s32(f2ord(fmaxf(mx0, mx1))));
            float lo = mn - CMAX, hi = mx + CMAX;
            float tau = 0.5f * (lo + hi);

            // fixed-count safeguarded Newton, 2^26 fixed-point REDUX (R10 core)
#pragma unroll 1
            for (int nit = 0; nit < NEWT; ++nit) {
                float s0 = 0.f, s1 = 0.f;
                int   ci = 0;
#pragma unroll
                for (int j = 0; j < 8; ++j) {
                    float z  = v[j] - tau;
                    float zc = fminf(fmaxf(z, -CMAX), CMAX);
                    ci += (fabsf(z) < CMAX) ? 1 : 0;
                    if (j & 1) s1 += zc; else s0 += zc;
                }
                int  sfix = rsum_s32(__float2int_rn((s0 + s1) * FS));
                int  cni  = rsum_s32(ci);
                float s  = (float)sfix * FSI;
                float cn = (float)cni;
                if (s > 1.f) lo = tau; else hi = tau;
                float tn = (cni >= 1) ? tau + __fdividef(s - 1.f, cn)
                                      : 0.5f * (lo + hi);
                if (!(tn > lo && tn < hi)) tn = 0.5f * (lo + hi);
                tau = tn;
            }

            // exact tau at the final active set (float-exact reduction):
            //   tau2 = (s + cn*tau - 1) / max(cn, 1)
            {
                float s0 = 0.f, s1 = 0.f;
                int   ci = 0;
#pragma unroll
                for (int j = 0; j < 8; ++j) {
                    float z  = v[j] - tau;
                    float zc = fminf(fmaxf(z, -CMAX), CMAX);
                    ci += (fabsf(z) < CMAX) ? 1 : 0;
                    if (j & 1) s1 += zc; else s0 += zc;
                }
                float s = s0 + s1;
#pragma unroll
                for (int o = 16; o > 0; o >>= 1)
                    s += __shfl_xor_sync(0xffffffffu, s, o);
                float cn = (float)rsum_s32(ci);
                tau = (s + cn * tau - 1.f) / fmaxf(cn, 1.f);
            }

            // FISTA momentum
            float tn   = 0.5f * (1.f + sqrtf(1.f + 4.f * tk * tk));
            float coef = (tk - 1.f) / tn;
            tk = tn;

            float yn_own = 0.f;
#pragma unroll
            for (int j = 0; j < 8; ++j) {
                float wn = fminf(fmaxf(v[j] - tau, -CMAX), CMAX);
                float yn = wn + coef * (wn - w_loc[j]);
                w_loc[j] = wn;
                y_loc[j] = yn;
                if (j == wid) yn_own = yn;
            }
            sy[lane + 32 * wid] = yn_own;   // disjoint owner writes
        }
        __syncthreads();
    }

    if (wid < 8) {
        float w_own = w_loc[0];
#pragma unroll
        for (int j = 1; j < 8; ++j) if (j == wid) w_own = w_loc[j];
        out[(size_t)b * 256 + lane + 32 * wid] = w_own;
    }
}

// ---------------------------------------------------------------------------
extern "C" void kernel_launch(void* const* d_in, const int* in_sizes, int n_in,
                              void* d_out, int out_size) {
    const float* A = (const float*)d_in[0];
    float* out = (float*)d_out;

    cudaFuncSetAttribute(fista_kernel,
                         cudaFuncAttributeMaxDynamicSharedMemorySize, SMEM_BYTES);

    qgemm_kernel<<<dim3(3, NB), 256>>>(A);
    fista_kernel<<<NB, TPB, SMEM_BYTES>>>(out);
}

// round 15
// speedup vs baseline: 1.0811x; 1.0811x over previous
#include <cuda_runtime.h>
#include <cuda_bf16.h>
#include <math.h>

// ---------------------------------------------------------------------------
#define NB      512
#define NA      256
#define CMAX    0.05f
#define NITERS  300
#define NPOW    30
#define NEWT    10      // Newton updates; a final exact evaluation follows

__device__ float dRf[(size_t)NB * 128 * 256];   // rows 0..127 of Q, full width
__device__ float dDf[(size_t)NB * 128 * 128];   // Q[128+i][128+j]

// integer warp reductions (sm_80+)
__device__ __forceinline__ int rsum_s32(int x) {
    int r;
    asm("redux.sync.add.s32 %0, %1, 0xffffffff;" : "=r"(r) : "r"(x));
    return r;
}
__device__ __forceinline__ int rmin_s32(int x) {
    int r;
    asm("redux.sync.min.s32 %0, %1, 0xffffffff;" : "=r"(r) : "r"(x));
    return r;
}
__device__ __forceinline__ int rmax_s32(int x) {
    int r;
    asm("redux.sync.max.s32 %0, %1, 0xffffffff;" : "=r"(r) : "r"(x));
    return r;
}
__device__ __forceinline__ int f2ord(float x) {
    int i = __float_as_int(x);
    return i ^ ((i >> 31) & 0x7fffffff);
}
__device__ __forceinline__ float ord2f(int i) {
    return __int_as_float(i ^ ((i >> 31) & 0x7fffffff));
}

// ---------------------------------------------------------------------------
// Kernel 1: Q = A^T A  (tiles (0,0),(0,1),(1,1); Q symmetric)
// ---------------------------------------------------------------------------
__global__ __launch_bounds__(256) void qgemm_kernel(const float* __restrict__ A) {
    const int tile = blockIdx.x;
    const int b    = blockIdx.y;
    const int cj   = (tile == 2) ? 128 : 0;
    const int ck   = (tile == 0) ? 0   : 128;

    __shared__ float sA[16][128];
    __shared__ float sB[16][128];

    const int tid = threadIdx.x;
    const int tx  = tid & 15;
    const int ty  = tid >> 4;

    float acc[8][8];
#pragma unroll
    for (int i = 0; i < 8; ++i)
#pragma unroll
        for (int j = 0; j < 8; ++j) acc[i][j] = 0.f;

    const float* __restrict__ Ab = A + (size_t)b * NA * NA;

    for (int ic = 0; ic < NA; ic += 16) {
#pragma unroll
        for (int u = 0; u < 2; ++u) {
            int idx = tid * 8 + u * 4;
            int r   = idx >> 7;
            int cc  = idx & 127;
            *(float4*)&sA[r][cc] = *(const float4*)&Ab[(size_t)(ic + r) * NA + cj + cc];
            *(float4*)&sB[r][cc] = *(const float4*)&Ab[(size_t)(ic + r) * NA + ck + cc];
        }
        __syncthreads();

#pragma unroll
        for (int kk = 0; kk < 16; ++kk) {
            float a8[8], b8[8];
            const float4* pa = (const float4*)&sA[kk][ty * 8];
            const float4* pb = (const float4*)&sB[kk][tx * 8];
            float4 a0 = pa[0], a1 = pa[1];
            float4 b0 = pb[0], b1 = pb[1];
            a8[0]=a0.x; a8[1]=a0.y; a8[2]=a0.z; a8[3]=a0.w;
            a8[4]=a1.x; a8[5]=a1.y; a8[6]=a1.z; a8[7]=a1.w;
            b8[0]=b0.x; b8[1]=b0.y; b8[2]=b0.z; b8[3]=b0.w;
            b8[4]=b1.x; b8[5]=b1.y; b8[6]=b1.z; b8[7]=b1.w;
#pragma unroll
            for (int i = 0; i < 8; ++i)
#pragma unroll
                for (int j = 0; j < 8; ++j)
                    acc[i][j] = fmaf(a8[i], b8[j], acc[i][j]);
        }
        __syncthreads();
    }

#pragma unroll
    for (int i = 0; i < 8; ++i) {
        int row = ty * 8 + i;
        float4 v0 = make_float4(acc[i][0], acc[i][1], acc[i][2], acc[i][3]);
        float4 v1 = make_float4(acc[i][4], acc[i][5], acc[i][6], acc[i][7]);
        if (tile < 2) {
            float* dst = dRf + ((size_t)b * 128 + row) * 256 + ck + tx * 8;
            *(float4*)dst       = v0;
            *(float4*)(dst + 4) = v1;
        } else {
            float* dst = dDf + ((size_t)b * 128 + row) * 128 + tx * 8;
            *(float4*)dst       = v0;
            *(float4*)(dst + 4) = v1;
        }
    }
}

// ---------------------------------------------------------------------------
// Kernel 2: per-batch FISTA. 1024 threads. Balanced matvec (R10 config).
// ---------------------------------------------------------------------------
#define TPB 1024
#define RP 260
#define DP 132
#define SR_ELEMS (128 * RP)
#define SD_ELEMS (128 * DP)
#define SP_ELEMS 1792
#define SMEM_FLOATS (SR_ELEMS + SD_ELEMS + 256 + SP_ELEMS + 32)
#define SMEM_BYTES (SMEM_FLOATS * 4)

__device__ __forceinline__ float blk_sum1024(float a, float* red, int t) {
#pragma unroll
    for (int o = 16; o > 0; o >>= 1)
        a += __shfl_xor_sync(0xffffffffu, a, o);
    if ((t & 31) == 0) red[t >> 5] = a;
    __syncthreads();
    float r = 0.f;
#pragma unroll
    for (int i = 0; i < 32; ++i) r += red[i];
    __syncthreads();
    return r;
}

// matvec producer: warps 0..15 rows of R (k-quarters), 16..23 rows of D,
// 24..31 R_ur^T row-major accumulation. Balanced float4 work per warp.
__device__ __forceinline__ void matvec_produce(const float* __restrict__ sR,
                                               const float* __restrict__ sD,
                                               const float* __restrict__ sy,
                                               float* __restrict__ sp,
                                               int wid, int lane) {
    const float4* __restrict__ y4 = (const float4*)sy;
    if (wid < 16) {
        const int q = wid >> 2;
        const int u = ((wid & 3) << 5) + lane;
        const float4* __restrict__ qr = (const float4*)(sR + u * RP) + q * 16;
        const float4* __restrict__ yy = y4 + q * 16;
        float g0 = 0.f, g1 = 0.f, g2 = 0.f, g3 = 0.f;
#pragma unroll
        for (int k = 0; k < 16; ++k) {
            float4 qv = qr[k], yv = yy[k];
            g0 = fmaf(qv.x, yv.x, g0); g1 = fmaf(qv.y, yv.y, g1);
            g2 = fmaf(qv.z, yv.z, g2); g3 = fmaf(qv.w, yv.w, g3);
        }
        sp[q * 128 + u] = (g0 + g1) + (g2 + g3);
    } else if (wid < 24) {
        const int w2 = wid - 16;
        const int hh = w2 >> 2;
        const int ul = ((w2 & 3) << 5) + lane;
        const float4* __restrict__ dr = (const float4*)(sD + ul * DP) + hh * 16;
        const float4* __restrict__ yy = y4 + 32 + hh * 16;
        float g0 = 0.f, g1 = 0.f, g2 = 0.f, g3 = 0.f;
#pragma unroll
        for (int k = 0; k < 16; ++k) {
            float4 qv = dr[k], yv = yy[k];
            g0 = fmaf(qv.x, yv.x, g0); g1 = fmaf(qv.y, yv.y, g1);
            g2 = fmaf(qv.z, yv.z, g2); g3 = fmaf(qv.w, yv.w, g3);
        }
        sp[512 + hh * 128 + ul] = (g0 + g1) + (g2 + g3);
    } else {
        const int w = wid - 24;
        const float4* __restrict__ sR4 = (const float4*)sR;
        float4 acc = make_float4(0.f, 0.f, 0.f, 0.f);
        const int k0 = w * 16;
#pragma unroll
        for (int kb = 0; kb < 4; ++kb) {
            float4 yv = y4[(k0 >> 2) + kb];
#pragma unroll
            for (int kk = 0; kk < 4; ++kk) {
                const int k = k0 + kb * 4 + kk;
                float4 qv = sR4[k * 65 + 32 + lane];   // R[k][128+4*lane ..]
                float yk = (kk == 0) ? yv.x : (kk == 1) ? yv.y
                          : (kk == 2) ? yv.z : yv.w;
                acc.x = fmaf(qv.x, yk, acc.x);
                acc.y = fmaf(qv.y, yk, acc.y);
                acc.z = fmaf(qv.z, yk, acc.z);
                acc.w = fmaf(qv.w, yk, acc.w);
            }
        }
        ((float4*)(sp + 768 + w * 128))[lane] = acc;
    }
}

// gather g_c from partials (lane-consecutive reads, conflict-free)
__device__ __forceinline__ float gather_g(const float* __restrict__ sp, int c) {
    if (c < 128) {
        return (sp[c] + sp[128 + c]) + (sp[256 + c] + sp[384 + c]);
    } else {
        const int cl = c - 128;
        float a = sp[512 + cl] + sp[640 + cl];
        float b0 = sp[768 + cl]  + sp[896 + cl];
        float b1 = sp[1024 + cl] + sp[1152 + cl];
        float b2 = sp[1280 + cl] + sp[1408 + cl];
        float b3 = sp[1536 + cl] + sp[1664 + cl];
        return a + ((b0 + b1) + (b2 + b3));
    }
}

__global__ __launch_bounds__(TPB, 1) void fista_kernel(float* __restrict__ out) {
    extern __shared__ float sm[];
    float* sR  = sm;
    float* sD  = sm + SR_ELEMS;
    float* sy  = sD + SD_ELEMS;          // 256
    float* sp  = sy + 256;               // 1792 partials
    float* red = sp + SP_ELEMS;          // 32

    const int b    = blockIdx.x;
    const int t    = threadIdx.x;
    const int lane = t & 31;
    const int wid  = t >> 5;             // 0..31

    // --- load compressed Q into padded SMEM ---
    {
        const float4* __restrict__ gR = (const float4*)(dRf + (size_t)b * 128 * 256);
        float4* sR4 = (float4*)sR;
        for (int i = t; i < 128 * 64; i += TPB) {
            int r = i >> 6, c = i & 63;
            sR4[r * 65 + c] = gR[i];
        }
        const float4* __restrict__ gD = (const float4*)(dDf + (size_t)b * 128 * 128);
        float4* sD4 = (float4*)sD;
        for (int i = t; i < 128 * 32; i += TPB) {
            int r = i >> 5, c = i & 31;
            sD4[r * 33 + c] = gD[i];
        }
    }
    if (t < 256) sy[t] = 0.0625f;   // 1/sqrt(256)
    __syncthreads();

    // --- power iteration for lambda_max ---
    for (int pi = 0; pi < NPOW; ++pi) {
        matvec_produce(sR, sD, sy, sp, wid, lane);
        __syncthreads();
        float g = (t < 256) ? gather_g(sp, t) : 0.f;
        float nr = blk_sum1024((t < 256) ? g * g : 0.f, red, t);
        if (t < 256) sy[t] = g * (1.f / (sqrtf(nr) + 1e-12f));
        __syncthreads();
    }
    float s2;
    {
        matvec_produce(sR, sD, sy, sp, wid, lane);
        __syncthreads();
        float g = (t < 256) ? gather_g(sp, t) : 0.f;
        float lmax = blk_sum1024((t < 256) ? sy[t] * g : 0.f, red, t);
        s2 = 2.f / (2.f * lmax + 1e-12f);
    }

    // --- FISTA ---
    const float FS  = 67108864.f;          // 2^26 fixed-point scale
    const float FSI = 1.f / 67108864.f;
    float w_loc[8], y_loc[8];
#pragma unroll
    for (int j = 0; j < 8; ++j) { w_loc[j] = 1.f / 256.f; y_loc[j] = 1.f / 256.f; }
    float tk = 1.f;
    if (t < 256) sy[t] = 1.f / 256.f;
    __syncthreads();

#pragma unroll 1
    for (int it = 0; it < NITERS; ++it) {
        matvec_produce(sR, sD, sy, sp, wid, lane);
        __syncthreads();

        if (wid < 8) {   // projection warps: each holds all 256 coords
            float v[8];
#pragma unroll
            for (int j = 0; j < 8; ++j) {
                int c = lane + 32 * j;
                v[j] = y_loc[j] - s2 * gather_g(sp, c);
            }

            // bracket via REDUX min/max on order-mapped ints
            float mn0 = fminf(fminf(v[0], v[1]), fminf(v[2], v[3]));
            float mn1 = fminf(fminf(v[4], v[5]), fminf(v[6], v[7]));
            float mx0 = fmaxf(fmaxf(v[0], v[1]), fmaxf(v[2], v[3]));
            float mx1 = fmaxf(fmaxf(v[4], v[5]), fmaxf(v[6], v[7]));
            float mn = ord2f(rmin_s32(f2ord(fminf(mn0, mn1))));
            float mx = ord2f(rmax_s32(f2ord(fmaxf(mx0, mx1))));
            float lo = mn - CMAX, hi = mx + CMAX;
            float tau = 0.5f * (lo + hi);

            // NEWT safeguarded Newton updates, 2^26 fixed-point REDUX
#pragma unroll 1
            for (int nit = 0; nit < NEWT; ++nit) {
                float s0 = 0.f, s1 = 0.f;
                int   ci = 0;
#pragma unroll
                for (int j = 0; j < 8; ++j) {
                    float z  = v[j] - tau;
                    float zc = fminf(fmaxf(z, -CMAX), CMAX);
                    ci += (fabsf(z) < CMAX) ? 1 : 0;
                    if (j & 1) s1 += zc; else s0 += zc;
                }
                int  sfix = rsum_s32(__float2int_rn((s0 + s1) * FS));
                int  cni  = rsum_s32(ci);
                float s  = (float)sfix * FSI;
                float cn = (float)cni;
                if (s > 1.f) lo = tau; else hi = tau;
                float tn = (cni >= 1) ? tau + __fdividef(s - 1.f, cn)
                                      : 0.5f * (lo + hi);
                if (!(tn > lo && tn < hi)) tn = 0.5f * (lo + hi);
                tau = tn;
            }

            // FINAL evaluation doubles as the exact active-set recompute:
            //   tau2 = (s + cn*tau - 1) / max(cn, 1)   (s float-exact via shfl)
            {
                float s0 = 0.f, s1 = 0.f;
                int   ci = 0;
#pragma unroll
                for (int j = 0; j < 8; ++j) {
                    float z  = v[j] - tau;
                    float zc = fminf(fmaxf(z, -CMAX), CMAX);
                    ci += (fabsf(z) < CMAX) ? 1 : 0;
                    if (j & 1) s1 += zc; else s0 += zc;
                }
                float s = s0 + s1;
#pragma unroll
                for (int o = 16; o > 0; o >>= 1)
                    s += __shfl_xor_sync(0xffffffffu, s, o);
                float cn = (float)rsum_s32(ci);
                tau = (s + cn * tau - 1.f) / fmaxf(cn, 1.f);
            }

            // FISTA momentum
            float tn   = 0.5f * (1.f + sqrtf(1.f + 4.f * tk * tk));
            float coef = (tk - 1.f) / tn;
            tk = tn;

            float yn_own = 0.f;
#pragma unroll
            for (int j = 0; j < 8; ++j) {
                float wn = fminf(fmaxf(v[j] - tau, -CMAX), CMAX);
                float yn = wn + coef * (wn - w_loc[j]);
                w_loc[j] = wn;
                y_loc[j] = yn;
                if (j == wid) yn_own = yn;
            }
            sy[lane + 32 * wid] = yn_own;   // disjoint owner writes
        }
        __syncthreads();
    }

    if (wid < 8) {
        float w_own = w_loc[0];
#pragma unroll
        for (int j = 1; j < 8; ++j) if (j == wid) w_own = w_loc[j];
        out[(size_t)b * 256 + lane + 32 * wid] = w_own;
    }
}

// ---------------------------------------------------------------------------
extern "C" void kernel_launch(void* const* d_in, const int* in_sizes, int n_in,
                              void* d_out, int out_size) {
    const float* A = (const float*)d_in[0];
    float* out = (float*)d_out;

    cudaFuncSetAttribute(fista_kernel,
                         cudaFuncAttributeMaxDynamicSharedMemorySize, SMEM_BYTES);

    qgemm_kernel<<<dim3(3, NB), 256>>>(A);
    fista_kernel<<<NB, TPB, SMEM_BYTES>>>(out);
}

// round 16
// speedup vs baseline: 1.1231x; 1.0389x over previous
#include <cuda_runtime.h>
#include <cuda_bf16.h>
#include <math.h>

// ---------------------------------------------------------------------------
#define NB      512
#define NA      256
#define CMAX    0.05f
#define NITERS  300
#define NPOW    30
#define NEWT    8       // mean-started Newton updates; final exact eval follows

__device__ float dRf[(size_t)NB * 128 * 256];   // rows 0..127 of Q, full width
__device__ float dDf[(size_t)NB * 128 * 128];   // Q[128+i][128+j]

// integer warp reductions (sm_80+)
__device__ __forceinline__ int rsum_s32(int x) {
    int r;
    asm("redux.sync.add.s32 %0, %1, 0xffffffff;" : "=r"(r) : "r"(x));
    return r;
}
__device__ __forceinline__ int rmin_s32(int x) {
    int r;
    asm("redux.sync.min.s32 %0, %1, 0xffffffff;" : "=r"(r) : "r"(x));
    return r;
}
__device__ __forceinline__ int rmax_s32(int x) {
    int r;
    asm("redux.sync.max.s32 %0, %1, 0xffffffff;" : "=r"(r) : "r"(x));
    return r;
}
__device__ __forceinline__ int f2ord(float x) {
    int i = __float_as_int(x);
    return i ^ ((i >> 31) & 0x7fffffff);
}
__device__ __forceinline__ float ord2f(int i) {
    return __int_as_float(i ^ ((i >> 31) & 0x7fffffff));
}

// ---------------------------------------------------------------------------
// Kernel 1: Q = A^T A  (tiles (0,0),(0,1),(1,1); Q symmetric)
// ---------------------------------------------------------------------------
__global__ __launch_bounds__(256) void qgemm_kernel(const float* __restrict__ A) {
    const int tile = blockIdx.x;
    const int b    = blockIdx.y;
    const int cj   = (tile == 2) ? 128 : 0;
    const int ck   = (tile == 0) ? 0   : 128;

    __shared__ float sA[16][128];
    __shared__ float sB[16][128];

    const int tid = threadIdx.x;
    const int tx  = tid & 15;
    const int ty  = tid >> 4;

    float acc[8][8];
#pragma unroll
    for (int i = 0; i < 8; ++i)
#pragma unroll
        for (int j = 0; j < 8; ++j) acc[i][j] = 0.f;

    const float* __restrict__ Ab = A + (size_t)b * NA * NA;

    for (int ic = 0; ic < NA; ic += 16) {
#pragma unroll
        for (int u = 0; u < 2; ++u) {
            int idx = tid * 8 + u * 4;
            int r   = idx >> 7;
            int cc  = idx & 127;
            *(float4*)&sA[r][cc] = *(const float4*)&Ab[(size_t)(ic + r) * NA + cj + cc];
            *(float4*)&sB[r][cc] = *(const float4*)&Ab[(size_t)(ic + r) * NA + ck + cc];
        }
        __syncthreads();

#pragma unroll
        for (int kk = 0; kk < 16; ++kk) {
            float a8[8], b8[8];
            const float4* pa = (const float4*)&sA[kk][ty * 8];
            const float4* pb = (const float4*)&sB[kk][tx * 8];
            float4 a0 = pa[0], a1 = pa[1];
            float4 b0 = pb[0], b1 = pb[1];
            a8[0]=a0.x; a8[1]=a0.y; a8[2]=a0.z; a8[3]=a0.w;
            a8[4]=a1.x; a8[5]=a1.y; a8[6]=a1.z; a8[7]=a1.w;
            b8[0]=b0.x; b8[1]=b0.y; b8[2]=b0.z; b8[3]=b0.w;
            b8[4]=b1.x; b8[5]=b1.y; b8[6]=b1.z; b8[7]=b1.w;
#pragma unroll
            for (int i = 0; i < 8; ++i)
#pragma unroll
                for (int j = 0; j < 8; ++j)
                    acc[i][j] = fmaf(a8[i], b8[j], acc[i][j]);
        }
        __syncthreads();
    }

#pragma unroll
    for (int i = 0; i < 8; ++i) {
        int row = ty * 8 + i;
        float4 v0 = make_float4(acc[i][0], acc[i][1], acc[i][2], acc[i][3]);
        float4 v1 = make_float4(acc[i][4], acc[i][5], acc[i][6], acc[i][7]);
        if (tile < 2) {
            float* dst = dRf + ((size_t)b * 128 + row) * 256 + ck + tx * 8;
            *(float4*)dst       = v0;
            *(float4*)(dst + 4) = v1;
        } else {
            float* dst = dDf + ((size_t)b * 128 + row) * 128 + tx * 8;
            *(float4*)dst       = v0;
            *(float4*)(dst + 4) = v1;
        }
    }
}

// ---------------------------------------------------------------------------
// Kernel 2: per-batch FISTA. 1024 threads. Balanced matvec (R10/R14 config).
// ---------------------------------------------------------------------------
#define TPB 1024
#define RP 260
#define DP 132
#define SR_ELEMS (128 * RP)
#define SD_ELEMS (128 * DP)
#define SP_ELEMS 1792
#define SMEM_FLOATS (SR_ELEMS + SD_ELEMS + 256 + SP_ELEMS + 32)
#define SMEM_BYTES (SMEM_FLOATS * 4)

__device__ __forceinline__ float blk_sum1024(float a, float* red, int t) {
#pragma unroll
    for (int o = 16; o > 0; o >>= 1)
        a += __shfl_xor_sync(0xffffffffu, a, o);
    if ((t & 31) == 0) red[t >> 5] = a;
    __syncthreads();
    float r0 = 0.f, r1 = 0.f, r2 = 0.f, r3 = 0.f;
#pragma unroll
    for (int i = 0; i < 8; ++i) {
        r0 += red[i];      r1 += red[i + 8];
        r2 += red[i + 16]; r3 += red[i + 24];
    }
    __syncthreads();
    return (r0 + r1) + (r2 + r3);
}

// matvec producer: warps 0..15 rows of R (k-quarters), 16..23 rows of D,
// 24..31 R_ur^T row-major accumulation. Balanced float4 work per warp.
__device__ __forceinline__ void matvec_produce(const float* __restrict__ sR,
                                               const float* __restrict__ sD,
                                               const float* __restrict__ sy,
                                               float* __restrict__ sp,
                                               int wid, int lane) {
    const float4* __restrict__ y4 = (const float4*)sy;
    if (wid < 16) {
        const int q = wid >> 2;
        const int u = ((wid & 3) << 5) + lane;
        const float4* __restrict__ qr = (const float4*)(sR + u * RP) + q * 16;
        const float4* __restrict__ yy = y4 + q * 16;
        float g0 = 0.f, g1 = 0.f, g2 = 0.f, g3 = 0.f;
#pragma unroll
        for (int k = 0; k < 16; ++k) {
            float4 qv = qr[k], yv = yy[k];
            g0 = fmaf(qv.x, yv.x, g0); g1 = fmaf(qv.y, yv.y, g1);
            g2 = fmaf(qv.z, yv.z, g2); g3 = fmaf(qv.w, yv.w, g3);
        }
        sp[q * 128 + u] = (g0 + g1) + (g2 + g3);
    } else if (wid < 24) {
        const int w2 = wid - 16;
        const int hh = w2 >> 2;
        const int ul = ((w2 & 3) << 5) + lane;
        const float4* __restrict__ dr = (const float4*)(sD + ul * DP) + hh * 16;
        const float4* __restrict__ yy = y4 + 32 + hh * 16;
        float g0 = 0.f, g1 = 0.f, g2 = 0.f, g3 = 0.f;
#pragma unroll
        for (int k = 0; k < 16; ++k) {
            float4 qv = dr[k], yv = yy[k];
            g0 = fmaf(qv.x, yv.x, g0); g1 = fmaf(qv.y, yv.y, g1);
            g2 = fmaf(qv.z, yv.z, g2); g3 = fmaf(qv.w, yv.w, g3);
        }
        sp[512 + hh * 128 + ul] = (g0 + g1) + (g2 + g3);
    } else {
        const int w = wid - 24;
        const float4* __restrict__ sR4 = (const float4*)sR;
        float4 acc = make_float4(0.f, 0.f, 0.f, 0.f);
        const int k0 = w * 16;
#pragma unroll
        for (int kb = 0; kb < 4; ++kb) {
            float4 yv = y4[(k0 >> 2) + kb];
#pragma unroll
            for (int kk = 0; kk < 4; ++kk) {
                const int k = k0 + kb * 4 + kk;
                float4 qv = sR4[k * 65 + 32 + lane];   // R[k][128+4*lane ..]
                float yk = (kk == 0) ? yv.x : (kk == 1) ? yv.y
                          : (kk == 2) ? yv.z : yv.w;
                acc.x = fmaf(qv.x, yk, acc.x);
                acc.y = fmaf(qv.y, yk, acc.y);
                acc.z = fmaf(qv.z, yk, acc.z);
                acc.w = fmaf(qv.w, yk, acc.w);
            }
        }
        ((float4*)(sp + 768 + w * 128))[lane] = acc;
    }
}

// gather g_c from partials (lane-consecutive reads, conflict-free)
__device__ __forceinline__ float gather_g(const float* __restrict__ sp, int c) {
    if (c < 128) {
        return (sp[c] + sp[128 + c]) + (sp[256 + c] + sp[384 + c]);
    } else {
        const int cl = c - 128;
        float a = sp[512 + cl] + sp[640 + cl];
        float b0 = sp[768 + cl]  + sp[896 + cl];
        float b1 = sp[1024 + cl] + sp[1152 + cl];
        float b2 = sp[1280 + cl] + sp[1408 + cl];
        float b3 = sp[1536 + cl] + sp[1664 + cl];
        return a + ((b0 + b1) + (b2 + b3));
    }
}

__global__ __launch_bounds__(TPB, 1) void fista_kernel(float* __restrict__ out) {
    extern __shared__ float sm[];
    float* sR  = sm;
    float* sD  = sm + SR_ELEMS;
    float* sy  = sD + SD_ELEMS;          // 256
    float* sp  = sy + 256;               // 1792 partials
    float* red = sp + SP_ELEMS;          // 32

    const int b    = blockIdx.x;
    const int t    = threadIdx.x;
    const int lane = t & 31;
    const int wid  = t >> 5;             // 0..31

    // --- load compressed Q into padded SMEM ---
    {
        const float4* __restrict__ gR = (const float4*)(dRf + (size_t)b * 128 * 256);
        float4* sR4 = (float4*)sR;
        for (int i = t; i < 128 * 64; i += TPB) {
            int r = i >> 6, c = i & 63;
            sR4[r * 65 + c] = gR[i];
        }
        const float4* __restrict__ gD = (const float4*)(dDf + (size_t)b * 128 * 128);
        float4* sD4 = (float4*)sD;
        for (int i = t; i < 128 * 32; i += TPB) {
            int r = i >> 5, c = i & 31;
            sD4[r * 33 + c] = gD[i];
        }
    }
    if (t < 256) sy[t] = 0.0625f;   // 1/sqrt(256)
    __syncthreads();

    // --- power iteration for lambda_max ---
    for (int pi = 0; pi < NPOW; ++pi) {
        matvec_produce(sR, sD, sy, sp, wid, lane);
        __syncthreads();
        float g = (t < 256) ? gather_g(sp, t) : 0.f;
        float nr = blk_sum1024((t < 256) ? g * g : 0.f, red, t);
        if (t < 256) sy[t] = g * (1.f / (sqrtf(nr) + 1e-12f));
        __syncthreads();
    }
    float s2;
    {
        matvec_produce(sR, sD, sy, sp, wid, lane);
        __syncthreads();
        float g = (t < 256) ? gather_g(sp, t) : 0.f;
        float lmax = blk_sum1024((t < 256) ? sy[t] * g : 0.f, red, t);
        s2 = 2.f / (2.f * lmax + 1e-12f);
    }

    // --- FISTA ---
    const float FS  = 67108864.f;          // 2^26 fixed-point scale
    const float FSI = 1.f / 67108864.f;
    float w_loc[8], y_loc[8];
#pragma unroll
    for (int j = 0; j < 8; ++j) { w_loc[j] = 1.f / 256.f; y_loc[j] = 1.f / 256.f; }
    float tk = 1.f;
    if (t < 256) sy[t] = 1.f / 256.f;
    __syncthreads();

#pragma unroll 1
    for (int it = 0; it < NITERS; ++it) {
        matvec_produce(sR, sD, sy, sp, wid, lane);
        __syncthreads();

        if (wid < 8) {   // projection warps: each holds all 256 coords
            // FISTA momentum scalars (tau-independent; hoisted for ILP)
            float tn   = 0.5f * (1.f + sqrtf(1.f + 4.f * tk * tk));
            float coef = (tk - 1.f) / tn;
            tk = tn;

            float v[8];
            float sv_loc = 0.f;
#pragma unroll
            for (int j = 0; j < 8; ++j) {
                int c = lane + 32 * j;
                v[j] = y_loc[j] - s2 * gather_g(sp, c);
                sv_loc += v[j];
            }

            // bracket via REDUX min/max on order-mapped ints
            float mn0 = fminf(fminf(v[0], v[1]), fminf(v[2], v[3]));
            float mn1 = fminf(fminf(v[4], v[5]), fminf(v[6], v[7]));
            float mx0 = fmaxf(fmaxf(v[0], v[1]), fmaxf(v[2], v[3]));
            float mx1 = fmaxf(fmaxf(v[4], v[5]), fmaxf(v[6], v[7]));
            float mn = ord2f(rmin_s32(f2ord(fminf(mn0, mn1))));
            float mx = ord2f(rmax_s32(f2ord(fmaxf(mx0, mx1))));
            float lo = mn - CMAX, hi = mx + CMAX;

            // mean start: tau0 = (sum(v) - 1)/256 (exact root if nothing clips)
            float sv = (float)rsum_s32(__float2int_rn(sv_loc * FS)) * FSI;
            float tau = (sv - 1.f) * (1.f / 256.f);
            if (!(tau > lo && tau < hi)) tau = 0.5f * (lo + hi);

            // NEWT safeguarded Newton updates, 2^26 fixed-point REDUX
#pragma unroll 1
            for (int nit = 0; nit < NEWT; ++nit) {
                float s0 = 0.f, s1 = 0.f;
                int   ci = 0;
#pragma unroll
                for (int j = 0; j < 8; ++j) {
                    float z  = v[j] - tau;
                    float zc = fminf(fmaxf(z, -CMAX), CMAX);
                    ci += (fabsf(z) < CMAX) ? 1 : 0;
                    if (j & 1) s1 += zc; else s0 += zc;
                }
                int  sfix = rsum_s32(__float2int_rn((s0 + s1) * FS));
                int  cni  = rsum_s32(ci);
                float s  = (float)sfix * FSI;
                float cn = (float)cni;
                if (s > 1.f) lo = tau; else hi = tau;
                float tu = (cni >= 1) ? tau + __fdividef(s - 1.f, cn)
                                      : 0.5f * (lo + hi);
                if (!(tu > lo && tu < hi)) tu = 0.5f * (lo + hi);
                tau = tu;
            }

            // FINAL evaluation doubles as the exact active-set recompute:
            //   tau2 = (s + cn*tau - 1) / max(cn, 1)   (s float-exact via shfl)
            {
                float s0 = 0.f, s1 = 0.f;
                int   ci = 0;
#pragma unroll
                for (int j = 0; j < 8; ++j) {
                    float z  = v[j] - tau;
                    float zc = fminf(fmaxf(z, -CMAX), CMAX);
                    ci += (fabsf(z) < CMAX) ? 1 : 0;
                    if (j & 1) s1 += zc; else s0 += zc;
                }
                float s = s0 + s1;
#pragma unroll
                for (int o = 16; o > 0; o >>= 1)
                    s += __shfl_xor_sync(0xffffffffu, s, o);
                float cn = (float)rsum_s32(ci);
                tau = (s + cn * tau - 1.f) / fmaxf(cn, 1.f);
            }

            float yn_own = 0.f;
#pragma unroll
            for (int j = 0; j < 8; ++j) {
                float wn = fminf(fmaxf(v[j] - tau, -CMAX), CMAX);
                float yn = wn + coef * (wn - w_loc[j]);
                w_loc[j] = wn;
                y_loc[j] = yn;
                if (j == wid) yn_own = yn;
            }
            sy[lane + 32 * wid] = yn_own;   // disjoint owner writes
        }
        __syncthreads();
    }

    if (wid < 8) {
        float w_own = w_loc[0];
#pragma unroll
        for (int j = 1; j < 8; ++j) if (j == wid) w_own = w_loc[j];
        out[(size_t)b * 256 + lane + 32 * wid] = w_own;
    }
}

// ---------------------------------------------------------------------------
extern "C" void kernel_launch(void* const* d_in, const int* in_sizes, int n_in,
                              void* d_out, int out_size) {
    const float* A = (const float*)d_in[0];
    float* out = (float*)d_out;

    cudaFuncSetAttribute(fista_kernel,
                         cudaFuncAttributeMaxDynamicSharedMemorySize, SMEM_BYTES);

    qgemm_kernel<<<dim3(3, NB), 256>>>(A);
    fista_kernel<<<NB, TPB, SMEM_BYTES>>>(out);
}

// round 17
// speedup vs baseline: 1.1547x; 1.0281x over previous
#include <cuda_runtime.h>
#include <cuda_bf16.h>
#include <math.h>

// ---------------------------------------------------------------------------
#define NB      512
#define NA      256
#define CMAX    0.05f
#define NITERS  300
#define NPOW    30
#define NEWT    8       // mean-started Newton updates; final exact eval follows

__device__ float dRf[(size_t)NB * 128 * 256];   // rows 0..127 of Q, full width
__device__ float dDf[(size_t)NB * 128 * 128];   // Q[128+i][128+j]

// integer warp reductions (sm_80+)
__device__ __forceinline__ int rsum_s32(int x) {
    int r;
    asm("redux.sync.add.s32 %0, %1, 0xffffffff;" : "=r"(r) : "r"(x));
    return r;
}
__device__ __forceinline__ int rmin_s32(int x) {
    int r;
    asm("redux.sync.min.s32 %0, %1, 0xffffffff;" : "=r"(r) : "r"(x));
    return r;
}
__device__ __forceinline__ int rmax_s32(int x) {
    int r;
    asm("redux.sync.max.s32 %0, %1, 0xffffffff;" : "=r"(r) : "r"(x));
    return r;
}
__device__ __forceinline__ int f2ord(float x) {
    int i = __float_as_int(x);
    return i ^ ((i >> 31) & 0x7fffffff);
}
__device__ __forceinline__ float ord2f(int i) {
    return __int_as_float(i ^ ((i >> 31) & 0x7fffffff));
}

// ---------------------------------------------------------------------------
// Kernel 1: Q = A^T A  (tiles (0,0),(0,1),(1,1); Q symmetric)
// ---------------------------------------------------------------------------
__global__ __launch_bounds__(256) void qgemm_kernel(const float* __restrict__ A) {
    const int tile = blockIdx.x;
    const int b    = blockIdx.y;
    const int cj   = (tile == 2) ? 128 : 0;
    const int ck   = (tile == 0) ? 0   : 128;

    __shared__ float sA[16][128];
    __shared__ float sB[16][128];

    const int tid = threadIdx.x;
    const int tx  = tid & 15;
    const int ty  = tid >> 4;

    float acc[8][8];
#pragma unroll
    for (int i = 0; i < 8; ++i)
#pragma unroll
        for (int j = 0; j < 8; ++j) acc[i][j] = 0.f;

    const float* __restrict__ Ab = A + (size_t)b * NA * NA;

    for (int ic = 0; ic < NA; ic += 16) {
#pragma unroll
        for (int u = 0; u < 2; ++u) {
            int idx = tid * 8 + u * 4;
            int r   = idx >> 7;
            int cc  = idx & 127;
            *(float4*)&sA[r][cc] = *(const float4*)&Ab[(size_t)(ic + r) * NA + cj + cc];
            *(float4*)&sB[r][cc] = *(const float4*)&Ab[(size_t)(ic + r) * NA + ck + cc];
        }
        __syncthreads();

#pragma unroll
        for (int kk = 0; kk < 16; ++kk) {
            float a8[8], b8[8];
            const float4* pa = (const float4*)&sA[kk][ty * 8];
            const float4* pb = (const float4*)&sB[kk][tx * 8];
            float4 a0 = pa[0], a1 = pa[1];
            float4 b0 = pb[0], b1 = pb[1];
            a8[0]=a0.x; a8[1]=a0.y; a8[2]=a0.z; a8[3]=a0.w;
            a8[4]=a1.x; a8[5]=a1.y; a8[6]=a1.z; a8[7]=a1.w;
            b8[0]=b0.x; b8[1]=b0.y; b8[2]=b0.z; b8[3]=b0.w;
            b8[4]=b1.x; b8[5]=b1.y; b8[6]=b1.z; b8[7]=b1.w;
#pragma unroll
            for (int i = 0; i < 8; ++i)
#pragma unroll
                for (int j = 0; j < 8; ++j)
                    acc[i][j] = fmaf(a8[i], b8[j], acc[i][j]);
        }
        __syncthreads();
    }

#pragma unroll
    for (int i = 0; i < 8; ++i) {
        int row = ty * 8 + i;
        float4 v0 = make_float4(acc[i][0], acc[i][1], acc[i][2], acc[i][3]);
        float4 v1 = make_float4(acc[i][4], acc[i][5], acc[i][6], acc[i][7]);
        if (tile < 2) {
            float* dst = dRf + ((size_t)b * 128 + row) * 256 + ck + tx * 8;
            *(float4*)dst       = v0;
            *(float4*)(dst + 4) = v1;
        } else {
            float* dst = dDf + ((size_t)b * 128 + row) * 128 + tx * 8;
            *(float4*)dst       = v0;
            *(float4*)(dst + 4) = v1;
        }
    }
}

// ---------------------------------------------------------------------------
// Kernel 2: per-batch FISTA. 1024 threads. Balanced matvec (R10/R15 config).
// ---------------------------------------------------------------------------
#define TPB 1024
#define RP 260
#define DP 132
#define SR_ELEMS (128 * RP)
#define SD_ELEMS (128 * DP)
#define SP_ELEMS 1792
#define SMEM_FLOATS (SR_ELEMS + SD_ELEMS + 256 + SP_ELEMS + 32)
#define SMEM_BYTES (SMEM_FLOATS * 4)

__device__ __forceinline__ float blk_sum1024(float a, float* red, int t) {
#pragma unroll
    for (int o = 16; o > 0; o >>= 1)
        a += __shfl_xor_sync(0xffffffffu, a, o);
    if ((t & 31) == 0) red[t >> 5] = a;
    __syncthreads();
    float r0 = 0.f, r1 = 0.f, r2 = 0.f, r3 = 0.f;
#pragma unroll
    for (int i = 0; i < 8; ++i) {
        r0 += red[i];      r1 += red[i + 8];
        r2 += red[i + 16]; r3 += red[i + 24];
    }
    __syncthreads();
    return (r0 + r1) + (r2 + r3);
}

// matvec producer: warps 0..15 rows of R (k-quarters), 16..23 rows of D,
// 24..31 R_ur^T row-major accumulation. Balanced float4 work per warp.
__device__ __forceinline__ void matvec_produce(const float* __restrict__ sR,
                                               const float* __restrict__ sD,
                                               const float* __restrict__ sy,
                                               float* __restrict__ sp,
                                               int wid, int lane) {
    const float4* __restrict__ y4 = (const float4*)sy;
    if (wid < 16) {
        const int q = wid >> 2;
        const int u = ((wid & 3) << 5) + lane;
        const float4* __restrict__ qr = (const float4*)(sR + u * RP) + q * 16;
        const float4* __restrict__ yy = y4 + q * 16;
        float g0 = 0.f, g1 = 0.f, g2 = 0.f, g3 = 0.f;
#pragma unroll
        for (int k = 0; k < 16; ++k) {
            float4 qv = qr[k], yv = yy[k];
            g0 = fmaf(qv.x, yv.x, g0); g1 = fmaf(qv.y, yv.y, g1);
            g2 = fmaf(qv.z, yv.z, g2); g3 = fmaf(qv.w, yv.w, g3);
        }
        sp[q * 128 + u] = (g0 + g1) + (g2 + g3);
    } else if (wid < 24) {
        const int w2 = wid - 16;
        const int hh = w2 >> 2;
        const int ul = ((w2 & 3) << 5) + lane;
        const float4* __restrict__ dr = (const float4*)(sD + ul * DP) + hh * 16;
        const float4* __restrict__ yy = y4 + 32 + hh * 16;
        float g0 = 0.f, g1 = 0.f, g2 = 0.f, g3 = 0.f;
#pragma unroll
        for (int k = 0; k < 16; ++k) {
            float4 qv = dr[k], yv = yy[k];
            g0 = fmaf(qv.x, yv.x, g0); g1 = fmaf(qv.y, yv.y, g1);
            g2 = fmaf(qv.z, yv.z, g2); g3 = fmaf(qv.w, yv.w, g3);
        }
        sp[512 + hh * 128 + ul] = (g0 + g1) + (g2 + g3);
    } else {
        const int w = wid - 24;
        const float4* __restrict__ sR4 = (const float4*)sR;
        float4 acc = make_float4(0.f, 0.f, 0.f, 0.f);
        const int k0 = w * 16;
#pragma unroll
        for (int kb = 0; kb < 4; ++kb) {
            float4 yv = y4[(k0 >> 2) + kb];
#pragma unroll
            for (int kk = 0; kk < 4; ++kk) {
                const int k = k0 + kb * 4 + kk;
                float4 qv = sR4[k * 65 + 32 + lane];   // R[k][128+4*lane ..]
                float yk = (kk == 0) ? yv.x : (kk == 1) ? yv.y
                          : (kk == 2) ? yv.z : yv.w;
                acc.x = fmaf(qv.x, yk, acc.x);
                acc.y = fmaf(qv.y, yk, acc.y);
                acc.z = fmaf(qv.z, yk, acc.z);
                acc.w = fmaf(qv.w, yk, acc.w);
            }
        }
        ((float4*)(sp + 768 + w * 128))[lane] = acc;
    }
}

// gather g_c from partials (lane-consecutive reads, conflict-free)
__device__ __forceinline__ float gather_g(const float* __restrict__ sp, int c) {
    if (c < 128) {
        return (sp[c] + sp[128 + c]) + (sp[256 + c] + sp[384 + c]);
    } else {
        const int cl = c - 128;
        float a = sp[512 + cl] + sp[640 + cl];
        float b0 = sp[768 + cl]  + sp[896 + cl];
        float b1 = sp[1024 + cl] + sp[1152 + cl];
        float b2 = sp[1280 + cl] + sp[1408 + cl];
        float b3 = sp[1536 + cl] + sp[1664 + cl];
        return a + ((b0 + b1) + (b2 + b3));
    }
}

__global__ __launch_bounds__(TPB, 1) void fista_kernel(float* __restrict__ out) {
    extern __shared__ float sm[];
    float* sR  = sm;
    float* sD  = sm + SR_ELEMS;
    float* sy  = sD + SD_ELEMS;          // 256
    float* sp  = sy + 256;               // 1792 partials
    float* red = sp + SP_ELEMS;          // 32

    const int b    = blockIdx.x;
    const int t    = threadIdx.x;
    const int lane = t & 31;
    const int wid  = t >> 5;             // 0..31

    // --- load compressed Q into padded SMEM ---
    {
        const float4* __restrict__ gR = (const float4*)(dRf + (size_t)b * 128 * 256);
        float4* sR4 = (float4*)sR;
        for (int i = t; i < 128 * 64; i += TPB) {
            int r = i >> 6, c = i & 63;
            sR4[r * 65 + c] = gR[i];
        }
        const float4* __restrict__ gD = (const float4*)(dDf + (size_t)b * 128 * 128);
        float4* sD4 = (float4*)sD;
        for (int i = t; i < 128 * 32; i += TPB) {
            int r = i >> 5, c = i & 31;
            sD4[r * 33 + c] = gD[i];
        }
    }
    if (t < 256) sy[t] = 0.0625f;   // 1/sqrt(256)
    __syncthreads();

    // --- power iteration for lambda_max ---
    for (int pi = 0; pi < NPOW; ++pi) {
        matvec_produce(sR, sD, sy, sp, wid, lane);
        __syncthreads();
        float g = (t < 256) ? gather_g(sp, t) : 0.f;
        float nr = blk_sum1024((t < 256) ? g * g : 0.f, red, t);
        if (t < 256) sy[t] = g * (1.f / (sqrtf(nr) + 1e-12f));
        __syncthreads();
    }
    float s2;
    {
        matvec_produce(sR, sD, sy, sp, wid, lane);
        __syncthreads();
        float g = (t < 256) ? gather_g(sp, t) : 0.f;
        float lmax = blk_sum1024((t < 256) ? sy[t] * g : 0.f, red, t);
        s2 = 2.f / (2.f * lmax + 1e-12f);
    }

    // --- FISTA ---
    const float FS   = 67108864.f;         // 2^26 fixed-point scale
    const float FSI  = 1.f / 67108864.f;
    const int   ONE_FIX = 1 << 26;         // 1.0 in fixed point
    float w_loc[8], y_loc[8];
#pragma unroll
    for (int j = 0; j < 8; ++j) { w_loc[j] = 1.f / 256.f; y_loc[j] = 1.f / 256.f; }
    float tk = 1.f;
    if (t < 256) sy[t] = 1.f / 256.f;
    __syncthreads();

#pragma unroll 1
    for (int it = 0; it < NITERS; ++it) {
        matvec_produce(sR, sD, sy, sp, wid, lane);
        __syncthreads();

        if (wid < 8) {   // projection warps: each holds all 256 coords
            // FISTA momentum scalars (tau-independent; hoisted for ILP)
            float tn   = 0.5f * (1.f + sqrtf(1.f + 4.f * tk * tk));
            float coef = (tk - 1.f) / tn;
            tk = tn;

            float v[8];
            float sv_loc = 0.f;
#pragma unroll
            for (int j = 0; j < 8; ++j) {
                int c = lane + 32 * j;
                v[j] = y_loc[j] - s2 * gather_g(sp, c);
                sv_loc += v[j];
            }

            // bracket via REDUX min/max on order-mapped ints
            float mn0 = fminf(fminf(v[0], v[1]), fminf(v[2], v[3]));
            float mn1 = fminf(fminf(v[4], v[5]), fminf(v[6], v[7]));
            float mx0 = fmaxf(fmaxf(v[0], v[1]), fmaxf(v[2], v[3]));
            float mx1 = fmaxf(fmaxf(v[4], v[5]), fmaxf(v[6], v[7]));
            float mn = ord2f(rmin_s32(f2ord(fminf(mn0, mn1))));
            float mx = ord2f(rmax_s32(f2ord(fmaxf(mx0, mx1))));
            float lo = mn - CMAX, hi = mx + CMAX;

            // mean start: tau0 = (sum(v) - 1)/256 (exact root if nothing clips)
            float sv = (float)rsum_s32(__float2int_rn(sv_loc * FS)) * FSI;
            float tau = (sv - 1.f) * (1.f / 256.f);
            if (!(tau > lo && tau < hi)) tau = 0.5f * (lo + hi);

            // NEWT safeguarded Newton updates, 2^26 fixed-point REDUX.
            // Bracket compare stays in the int domain (s > 1 <=> sfix > 2^26)
            // so the safeguard path doesn't wait on the I2F.
#pragma unroll 1
            for (int nit = 0; nit < NEWT; ++nit) {
                float s0 = 0.f, s1 = 0.f;
                int   ci = 0;
#pragma unroll
                for (int j = 0; j < 8; ++j) {
                    float z  = v[j] - tau;
                    float zc = fminf(fmaxf(z, -CMAX), CMAX);
                    ci += (fabsf(z) < CMAX) ? 1 : 0;
                    if (j & 1) s1 += zc; else s0 += zc;
                }
                int  sfix = rsum_s32(__float2int_rn((s0 + s1) * FS));
                int  cni  = rsum_s32(ci);
                if (sfix > ONE_FIX) lo = tau; else hi = tau;
                float s  = (float)sfix * FSI;
                float cn = (float)cni;
                float tu = (cni >= 1) ? tau + __fdividef(s - 1.f, cn)
                                      : 0.5f * (lo + hi);
                if (!(tu > lo && tu < hi)) tu = 0.5f * (lo + hi);
                tau = tu;
            }

            // FINAL evaluation doubles as the exact active-set recompute:
            //   tau2 = (s + cn*tau - 1) / max(cn, 1)
            // s via 2^26 fixed-point REDUX: s error <= 2.4e-7, divided by cn
            // -> tau error ~1e-9 (negligible vs the Newton-depth error).
            {
                float s0 = 0.f, s1 = 0.f;
                int   ci = 0;
#pragma unroll
                for (int j = 0; j < 8; ++j) {
                    float z  = v[j] - tau;
                    float zc = fminf(fmaxf(z, -CMAX), CMAX);
                    ci += (fabsf(z) < CMAX) ? 1 : 0;
                    if (j & 1) s1 += zc; else s0 += zc;
                }
                int  sfix = rsum_s32(__float2int_rn((s0 + s1) * FS));
                int  cni  = rsum_s32(ci);
                float s  = (float)sfix * FSI;
                float cn = (float)cni;
                tau = (s + cn * tau - 1.f) / fmaxf(cn, 1.f);
            }

            float yn_own = 0.f;
#pragma unroll
            for (int j = 0; j < 8; ++j) {
                float wn = fminf(fmaxf(v[j] - tau, -CMAX), CMAX);
                float yn = wn + coef * (wn - w_loc[j]);
                w_loc[j] = wn;
                y_loc[j] = yn;
                if (j == wid) yn_own = yn;
            }
            sy[lane + 32 * wid] = yn_own;   // disjoint owner writes
        }
        __syncthreads();
    }

    if (wid < 8) {
        float w_own = w_loc[0];
#pragma unroll
        for (int j = 1; j < 8; ++j) if (j == wid) w_own = w_loc[j];
        out[(size_t)b * 256 + lane + 32 * wid] = w_own;
    }
}

// ---------------------------------------------------------------------------
extern "C" void kernel_launch(void* const* d_in, const int* in_sizes, int n_in,
                              void* d_out, int out_size) {
    const float* A = (const float*)d_in[0];
    float* out = (float*)d_out;

    cudaFuncSetAttribute(fista_kernel,
                         cudaFuncAttributeMaxDynamicSharedMemorySize, SMEM_BYTES);

    qgemm_kernel<<<dim3(3, NB), 256>>>(A);
    fista_kernel<<<NB, TPB, SMEM_BYTES>>>(out);
}